// round 15
// baseline (speedup 1.0000x reference)
#include <cuda_runtime.h>
#include <cstddef>
#include <cstdint>

// Problem constants
#define Bb 8
#define Np 8192
#define Mp 1024
#define Cc 256
#define Rr (Bb*Np)       // 65536 rows
#define BN_EPS 1e-5f

// Scratch (static __device__ — no allocations allowed)
__device__ float g_bufA[(size_t)Rr*Cc];     // 64 MB
__device__ float g_bufB[(size_t)Rr*Cc];     // 64 MB
__device__ float g_xT[(size_t)Bb*Mp*Cc];    // 8 MB
__device__ int4   g_idx[Rr];                // 1 MB: global neighbor indices (b*Mp+m)
__device__ float4 g_wt[Rr];                 // 1 MB: interpolation weights
__device__ float g_sum0[Cc],  g_sumsq0[Cc];
__device__ float g_sum1[Cc],  g_sumsq1[Cc];
__device__ float g_sum2[Cc],  g_sumsq2[Cc];
__device__ float g_scale[Cc];
__device__ float g_shift[Cc];

// ---------------------------------------------------------------------------
__global__ void zero_stats_kernel() {
    int t = threadIdx.x;
    g_sum0[t] = 0.f; g_sumsq0[t] = 0.f;
    g_sum1[t] = 0.f; g_sumsq1[t] = 0.f;
    g_sum2[t] = 0.f; g_sumsq2[t] = 0.f;
}

// fold BN into per-channel affine from raw sums: one tiny launch per layer
__global__ void bn_finalize_kernel(const float* __restrict__ sum,
                                   const float* __restrict__ sumsq,
                                   const float* __restrict__ g,
                                   const float* __restrict__ beta, int O) {
    int t = threadIdx.x;
    if (t < O) {
        const float cnt = (float)Rr;
        float mu  = sum[t] / cnt;
        float var = fmaxf(sumsq[t] / cnt - mu * mu, 0.f);
        float sc  = rsqrtf(var + BN_EPS) * g[t];
        g_scale[t] = sc;
        g_shift[t] = beta[t] - mu * sc;
    }
}

// ---------------------------------------------------------------------------
// transpose x[b][c][m] -> xT[b][m][c]
__global__ void transpose_x_kernel(const float* __restrict__ x, float* __restrict__ xT) {
    __shared__ float t[32][33];
    int b = blockIdx.z;
    int m0 = blockIdx.x * 32, c0 = blockIdx.y * 32;
    int tx = threadIdx.x, ty = threadIdx.y; // 32 x 8
    const float* xb = x + (size_t)b * Cc * Mp;
    #pragma unroll
    for (int k = 0; k < 32; k += 8)
        t[ty + k][tx] = xb[(size_t)(c0 + ty + k) * Mp + m0 + tx];
    __syncthreads();
    float* ob = xT + (size_t)b * Mp * Cc;
    #pragma unroll
    for (int k = 0; k < 32; k += 8)
        ob[(size_t)(m0 + ty + k) * Cc + c0 + tx] = t[tx][ty + k];
}

// ---------------------------------------------------------------------------
// 3-NN scan only: writes global neighbor indices + normalized inverse-distance
// weights. 256 threads: two threads split each point's 1024-scan (even/odd
// ILP chains each), merge in smem.
__global__ void knn_kernel(const float* __restrict__ p,
                           const float* __restrict__ q,
                           int4* __restrict__ idxOut,
                           float4* __restrict__ wtOut) {
    __shared__ float sqx[Mp], sqy[Mp], sqz[Mp], sqq[Mp];
    __shared__ float sd[256][3];
    __shared__ int   sdi[256][3];
    const int b = blockIdx.x;
    const int n0 = blockIdx.y * 128;
    const int tid = threadIdx.x;       // 256

    for (int m = tid; m < Mp; m += 256) {
        float qx = q[((size_t)b * Mp + m) * 3 + 0];
        float qy = q[((size_t)b * Mp + m) * 3 + 1];
        float qz = q[((size_t)b * Mp + m) * 3 + 2];
        sqx[m] = qx; sqy[m] = qy; sqz[m] = qz;
        sqq[m] = qx * qx + qy * qy + qz * qz;
    }
    __syncthreads();

    const int pt = tid & 127;
    const int half = tid >> 7;
    const int n = n0 + pt;
    float px = p[((size_t)b * Np + n) * 3 + 0];
    float py = p[((size_t)b * Np + n) * 3 + 1];
    float pz = p[((size_t)b * Np + n) * 3 + 2];
    float pp = px * px + py * py + pz * pz;

    float e0 = 3.4e38f, e1 = 3.4e38f, e2 = 3.4e38f;
    int   ei0 = 0, ei1 = 0, ei2 = 0;
    float o0 = 3.4e38f, o1 = 3.4e38f, o2 = 3.4e38f;
    int   oi0 = 0, oi1 = 0, oi2 = 0;
    const int mBase = half * 512;
    #pragma unroll 2
    for (int m = mBase; m < mBase + 512; m += 2) {
        float dotE = px * sqx[m] + py * sqy[m] + pz * sqz[m];
        float dE = pp + sqq[m] - 2.f * dotE;
        float dotO = px * sqx[m+1] + py * sqy[m+1] + pz * sqz[m+1];
        float dO = pp + sqq[m+1] - 2.f * dotO;
        if (dE < e2) {
            if (dE < e1) {
                e2 = e1; ei2 = ei1;
                if (dE < e0) { e1 = e0; ei1 = ei0; e0 = dE; ei0 = m; }
                else         { e1 = dE; ei1 = m; }
            } else { e2 = dE; ei2 = m; }
        }
        if (dO < o2) {
            if (dO < o1) {
                o2 = o1; oi2 = oi1;
                if (dO < o0) { o1 = o0; oi1 = oi0; o0 = dO; oi0 = m+1; }
                else         { o1 = dO; oi1 = m+1; }
            } else { o2 = dO; oi2 = m+1; }
        }
    }
    #pragma unroll
    for (int c = 0; c < 3; c++) {
        float d = (c == 0) ? o0 : (c == 1) ? o1 : o2;
        int   i = (c == 0) ? oi0 : (c == 1) ? oi1 : oi2;
        if (d < e2) {
            if (d < e1) {
                e2 = e1; ei2 = ei1;
                if (d < e0) { e1 = e0; ei1 = ei0; e0 = d; ei0 = i; }
                else        { e1 = d; ei1 = i; }
            } else { e2 = d; ei2 = i; }
        }
    }
    sd[tid][0] = e0;  sd[tid][1] = e1;  sd[tid][2] = e2;
    sdi[tid][0] = ei0; sdi[tid][1] = ei1; sdi[tid][2] = ei2;
    __syncthreads();

    if (tid < 128) {
        float m0 = sd[tid][0], m1 = sd[tid][1], m2 = sd[tid][2];
        int   j0 = sdi[tid][0], j1 = sdi[tid][1], j2 = sdi[tid][2];
        #pragma unroll
        for (int c = 0; c < 3; c++) {
            float d = sd[tid + 128][c];
            int   i = sdi[tid + 128][c];
            if (d < m2) {
                if (d < m1) {
                    m2 = m1; j2 = j1;
                    if (d < m0) { m1 = m0; j1 = j0; m0 = d; j0 = i; }
                    else        { m1 = d; j1 = i; }
                } else { m2 = d; j2 = i; }
            }
        }
        float a0 = 1.f / fmaxf(m0, 1e-10f);
        float a1 = 1.f / fmaxf(m1, 1e-10f);
        float a2 = 1.f / fmaxf(m2, 1e-10f);
        float inv = 1.f / (a0 + a1 + a2);
        const size_t row = (size_t)b * Np + n0 + tid;
        idxOut[row] = make_int4(b * Mp + j0, b * Mp + j1, b * Mp + j2, 0);
        wtOut[row]  = make_float4(a0 * inv, a1 * inv, a2 * inv, 0.f);
    }
}

// ---------------------------------------------------------------------------
// bf16x3 emulated-fp32 GEMM via legacy mma.sync (sm_80 PTX path)
// ---------------------------------------------------------------------------
__device__ __forceinline__ uint32_t prmt_hi(uint32_t a, uint32_t b) {
    uint32_t r; asm("prmt.b32 %0, %1, %2, 0x7632;" : "=r"(r) : "r"(a), "r"(b));
    return r;   // {lo16 = a.hi16, hi16 = b.hi16}
}
__device__ __forceinline__ uint32_t pack_bf16_rn(float lo0, float lo1) {
    uint32_t r; asm("cvt.rn.bf16x2.f32 %0, %1, %2;" : "=r"(r) : "f"(lo1), "f"(lo0));
    return r;   // low half = lo0
}
__device__ __forceinline__ float trunc_hi_f(float f) {
    return __uint_as_float(__float_as_uint(f) & 0xFFFF0000u);
}

#define MMA_BF16(c, a, b0v, b1v) \
    asm volatile("mma.sync.aligned.m16n8k16.row.col.f32.bf16.bf16.f32 " \
        "{%0,%1,%2,%3},{%4,%5,%6,%7},{%8,%9},{%0,%1,%2,%3};" \
        : "+f"((c)[0]), "+f"((c)[1]), "+f"((c)[2]), "+f"((c)[3]) \
        : "r"((a).x), "r"((a).y), "r"((a).z), "r"((a).w), "r"(b0v), "r"(b1v))

#define LDMATRIX_X4(r, addr) \
    asm volatile("ldmatrix.sync.aligned.m8n8.x4.shared.b16 {%0,%1,%2,%3}, [%4];" \
        : "=r"((r).x), "=r"((r).y), "=r"((r).z), "=r"((r).w) : "r"(addr))

// smem tiles: bf16, row-major, rows x 32 k = 64 B/row, XOR-granule swizzle.
// Stage layout: A_hi(4K) A_lo(4K) B_hi(8K) B_lo(8K) = 24 KB; 4 stages = 96 KB.
#define A_TILE   4096
#define B_TILE   8192
#define STAGE_B  (2 * A_TILE + 2 * B_TILE)   // 24576
#define SMEM_GEMM_BYTES (4 * STAGE_B)        // 98304

// out[r][o] = sum_c act(A[r][c]) * W[o][c] + bias[o], K=256, CTA tile 64x128.
// 256 threads, 8 warps (2M x 4N), 2 CTAs/SM, 4-stage ring, barrier per 2 kb.
// GATHER=1: A rows are gathered on the fly from xT via g_idx/g_wt (layer 0).
// GATHER=0: A read directly; prev-layer BN+ReLU from g_scale/g_shift if useAct.
// BN stats fused into epilogue.
template<int GATHER>
__global__ void __launch_bounds__(256, 2)
gemm_bf16x3_kernel(const float* __restrict__ A, const float* __restrict__ W,
                   const float* __restrict__ bias, int useAct,
                   float* __restrict__ out, int O,
                   float* __restrict__ sumArr, float* __restrict__ sumsqArr,
                   const int4* __restrict__ gIdx, const float4* __restrict__ gWt) {
    extern __shared__ char smc[];
    const int tid = threadIdx.x;
    const int lane = tid & 31, wid = tid >> 5;
    const int wm = wid >> 2, wn = wid & 3;           // 2M x 4N
    const size_t rowBase = (size_t)blockIdx.x * 64;
    const int colBase = blockIdx.y * 128;

    const uint32_t smb = (uint32_t)__cvta_generic_to_shared(smc);

    // producer mapping: prow = tid>>2 (0..63), pkg = tid&3 (8 k each)
    const int prow = tid >> 2;
    const int pkg = tid & 3;
    const uint32_t swz = (uint32_t)((pkg ^ ((prow >> 1) & 3)) << 4);
    const uint32_t aSlot  = (uint32_t)(prow * 64) + swz;
    const uint32_t bSlot0 = (uint32_t)(prow * 64) + swz;
    const uint32_t bSlot1 = (uint32_t)((prow + 64) * 64) +
                            (uint32_t)((pkg ^ (((prow + 64) >> 1) & 3)) << 4);
    const float* aG = A + (rowBase + prow) * 256 + pkg * 8;
    const float* wG0 = W + (size_t)(colBase + prow) * 256 + pkg * 8;
    const float* wG1 = W + (size_t)(colBase + prow + 64) * 256 + pkg * 8;

    // gather-mode loop-invariant state (layer 0)
    const float *gr0 = nullptr, *gr1 = nullptr, *gr2 = nullptr;
    float gw0 = 0.f, gw1 = 0.f, gw2 = 0.f;
    if (GATHER) {
        int4 id = gIdx[rowBase + prow];
        float4 wv = gWt[rowBase + prow];
        gr0 = A + (size_t)id.x * 256 + pkg * 8;
        gr1 = A + (size_t)id.y * 256 + pkg * 8;
        gr2 = A + (size_t)id.z * 256 + pkg * 8;
        gw0 = wv.x; gw1 = wv.y; gw2 = wv.z;
    }

    float acc[2][4][4];
    #pragma unroll
    for (int i = 0; i < 2; i++)
        #pragma unroll
        for (int j = 0; j < 4; j++)
            #pragma unroll
            for (int r = 0; r < 4; r++) acc[i][j][r] = 0.f;

    float4 va0, va1, vb0, vb1, vb2, vb3;
    auto loadG = [&](int kb) {
        if (GATHER) {
            float4 x0 = *(const float4*)(gr0 + kb * 32);
            float4 y0 = *(const float4*)(gr1 + kb * 32);
            float4 z0 = *(const float4*)(gr2 + kb * 32);
            float4 x1 = *(const float4*)(gr0 + kb * 32 + 4);
            float4 y1 = *(const float4*)(gr1 + kb * 32 + 4);
            float4 z1 = *(const float4*)(gr2 + kb * 32 + 4);
            va0.x = gw0 * x0.x + gw1 * y0.x + gw2 * z0.x;
            va0.y = gw0 * x0.y + gw1 * y0.y + gw2 * z0.y;
            va0.z = gw0 * x0.z + gw1 * y0.z + gw2 * z0.z;
            va0.w = gw0 * x0.w + gw1 * y0.w + gw2 * z0.w;
            va1.x = gw0 * x1.x + gw1 * y1.x + gw2 * z1.x;
            va1.y = gw0 * x1.y + gw1 * y1.y + gw2 * z1.y;
            va1.z = gw0 * x1.z + gw1 * y1.z + gw2 * z1.z;
            va1.w = gw0 * x1.w + gw1 * y1.w + gw2 * z1.w;
        } else {
            va0 = *(const float4*)(aG + kb * 32);
            va1 = *(const float4*)(aG + kb * 32 + 4);
        }
        vb0 = *(const float4*)(wG0 + kb * 32);
        vb1 = *(const float4*)(wG0 + kb * 32 + 4);
        vb2 = *(const float4*)(wG1 + kb * 32);
        vb3 = *(const float4*)(wG1 + kb * 32 + 4);
    };
    auto cvt8 = [&](const float* a, uint4& hi, uint4& lo) {
        hi.x = prmt_hi(__float_as_uint(a[0]), __float_as_uint(a[1]));
        hi.y = prmt_hi(__float_as_uint(a[2]), __float_as_uint(a[3]));
        hi.z = prmt_hi(__float_as_uint(a[4]), __float_as_uint(a[5]));
        hi.w = prmt_hi(__float_as_uint(a[6]), __float_as_uint(a[7]));
        lo.x = pack_bf16_rn(a[0] - trunc_hi_f(a[0]), a[1] - trunc_hi_f(a[1]));
        lo.y = pack_bf16_rn(a[2] - trunc_hi_f(a[2]), a[3] - trunc_hi_f(a[3]));
        lo.z = pack_bf16_rn(a[4] - trunc_hi_f(a[4]), a[5] - trunc_hi_f(a[5]));
        lo.w = pack_bf16_rn(a[6] - trunc_hi_f(a[6]), a[7] - trunc_hi_f(a[7]));
    };
    auto storeS = [&](int s, int kb) {
        const uint32_t stg = smb + s * STAGE_B;
        float a[8] = {va0.x, va0.y, va0.z, va0.w, va1.x, va1.y, va1.z, va1.w};
        if (!GATHER && useAct) {
            int c = kb * 32 + pkg * 8;
            #pragma unroll
            for (int j = 0; j < 8; j++)
                a[j] = fmaxf(fmaf(a[j], g_scale[c + j], g_shift[c + j]), 0.f);
        }
        uint4 hi, lo;
        cvt8(a, hi, lo);
        asm volatile("st.shared.v4.b32 [%0], {%1,%2,%3,%4};"
                     :: "r"(stg + aSlot), "r"(hi.x), "r"(hi.y), "r"(hi.z), "r"(hi.w));
        asm volatile("st.shared.v4.b32 [%0], {%1,%2,%3,%4};"
                     :: "r"(stg + A_TILE + aSlot), "r"(lo.x), "r"(lo.y), "r"(lo.z), "r"(lo.w));

        float b0a[8] = {vb0.x, vb0.y, vb0.z, vb0.w, vb1.x, vb1.y, vb1.z, vb1.w};
        cvt8(b0a, hi, lo);
        asm volatile("st.shared.v4.b32 [%0], {%1,%2,%3,%4};"
                     :: "r"(stg + 2 * A_TILE + bSlot0), "r"(hi.x), "r"(hi.y), "r"(hi.z), "r"(hi.w));
        asm volatile("st.shared.v4.b32 [%0], {%1,%2,%3,%4};"
                     :: "r"(stg + 2 * A_TILE + B_TILE + bSlot0), "r"(lo.x), "r"(lo.y), "r"(lo.z), "r"(lo.w));

        float b1a[8] = {vb2.x, vb2.y, vb2.z, vb2.w, vb3.x, vb3.y, vb3.z, vb3.w};
        cvt8(b1a, hi, lo);
        asm volatile("st.shared.v4.b32 [%0], {%1,%2,%3,%4};"
                     :: "r"(stg + 2 * A_TILE + bSlot1), "r"(hi.x), "r"(hi.y), "r"(hi.z), "r"(hi.w));
        asm volatile("st.shared.v4.b32 [%0], {%1,%2,%3,%4};"
                     :: "r"(stg + 2 * A_TILE + B_TILE + bSlot1), "r"(lo.x), "r"(lo.y), "r"(lo.z), "r"(lo.w));
    };

    const int aRow0 = wm * 32 + ((lane >> 3) & 1) * 8 + (lane & 7);
    const int aKh = (lane >> 4) & 1;
    const int bRow0 = wn * 32 + ((lane >> 4) & 1) * 8 + (lane & 7);
    const int bKh = (lane >> 3) & 1;
    uint32_t aOff[2][2], bOff[2][2];
    #pragma unroll
    for (int mt = 0; mt < 2; mt++) {
        int row = aRow0 + mt * 16;
        #pragma unroll
        for (int ks = 0; ks < 2; ks++)
            aOff[mt][ks] = (uint32_t)(row * 64 + ((((ks << 1) + aKh) ^ ((row >> 1) & 3)) << 4));
    }
    #pragma unroll
    for (int p = 0; p < 2; p++) {
        int row = bRow0 + p * 16;
        #pragma unroll
        for (int ks = 0; ks < 2; ks++)
            bOff[p][ks] = (uint32_t)(2 * A_TILE + row * 64 + ((((ks << 1) + bKh) ^ ((row >> 1) & 3)) << 4));
    }

    auto consume = [&](int s) {
        const uint32_t stg = smb + s * STAGE_B;
        uint4 ah[2], al[2], bh[2][2], bl[2][2];
        #pragma unroll
        for (int mt = 0; mt < 2; mt++) {
            LDMATRIX_X4(ah[mt], stg + aOff[mt][0]);
            LDMATRIX_X4(al[mt], stg + aOff[mt][0] + A_TILE);
        }
        #pragma unroll
        for (int p = 0; p < 2; p++) {
            LDMATRIX_X4(bh[0][p], stg + bOff[p][0]);
            LDMATRIX_X4(bl[0][p], stg + bOff[p][0] + B_TILE);
        }
        #pragma unroll
        for (int p = 0; p < 2; p++) {
            LDMATRIX_X4(bh[1][p], stg + bOff[p][1]);
            LDMATRIX_X4(bl[1][p], stg + bOff[p][1] + B_TILE);
        }
        #pragma unroll
        for (int mt = 0; mt < 2; mt++) {
            #pragma unroll
            for (int p = 0; p < 2; p++) {
                MMA_BF16(acc[mt][2*p],   ah[mt], bh[0][p].x, bh[0][p].y);
                MMA_BF16(acc[mt][2*p],   ah[mt], bl[0][p].x, bl[0][p].y);
                MMA_BF16(acc[mt][2*p],   al[mt], bh[0][p].x, bh[0][p].y);
                MMA_BF16(acc[mt][2*p+1], ah[mt], bh[0][p].z, bh[0][p].w);
                MMA_BF16(acc[mt][2*p+1], ah[mt], bl[0][p].z, bl[0][p].w);
                MMA_BF16(acc[mt][2*p+1], al[mt], bh[0][p].z, bh[0][p].w);
            }
        }
        #pragma unroll
        for (int mt = 0; mt < 2; mt++) {
            LDMATRIX_X4(ah[mt], stg + aOff[mt][1]);
            LDMATRIX_X4(al[mt], stg + aOff[mt][1] + A_TILE);
        }
        #pragma unroll
        for (int mt = 0; mt < 2; mt++) {
            #pragma unroll
            for (int p = 0; p < 2; p++) {
                MMA_BF16(acc[mt][2*p],   ah[mt], bh[1][p].x, bh[1][p].y);
                MMA_BF16(acc[mt][2*p],   ah[mt], bl[1][p].x, bl[1][p].y);
                MMA_BF16(acc[mt][2*p],   al[mt], bh[1][p].x, bh[1][p].y);
                MMA_BF16(acc[mt][2*p+1], ah[mt], bh[1][p].z, bh[1][p].w);
                MMA_BF16(acc[mt][2*p+1], ah[mt], bl[1][p].z, bl[1][p].w);
                MMA_BF16(acc[mt][2*p+1], al[mt], bh[1][p].z, bh[1][p].w);
            }
        }
    };

    // prologue
    loadG(0); storeS(0, 0);
    loadG(1); storeS(1, 1);
    __syncthreads();

    // mainloop: one barrier per 2 K-blocks
    #pragma unroll 1
    for (int kbp = 0; kbp < 8; kbp += 2) {
        if (kbp + 2 < 8) loadG(kbp + 2);
        consume(kbp & 3);
        if (kbp + 2 < 8) storeS((kbp + 2) & 3, kbp + 2);
        if (kbp + 3 < 8) loadG(kbp + 3);
        consume((kbp + 1) & 3);
        if (kbp + 3 < 8) storeS((kbp + 3) & 3, kbp + 3);
        if (kbp + 2 < 8) __syncthreads();
    }

    // epilogue: +bias, store, fused per-channel stats
    float sp[8], ssp[8];
    #pragma unroll
    for (int c = 0; c < 8; c++) { sp[c] = 0.f; ssp[c] = 0.f; }

    const int gId = lane >> 2, l4 = lane & 3;
    #pragma unroll
    for (int mt = 0; mt < 2; mt++) {
        size_t row0 = rowBase + wm * 32 + mt * 16 + gId;
        #pragma unroll
        for (int nt = 0; nt < 4; nt++) {
            int col0 = colBase + wn * 32 + nt * 8 + 2 * l4;
            float b0 = bias[col0], b1 = bias[col0 + 1];
            float v00 = acc[mt][nt][0] + b0, v01 = acc[mt][nt][1] + b1;
            float v10 = acc[mt][nt][2] + b0, v11 = acc[mt][nt][3] + b1;
            *(float2*)(out + row0 * O + col0)        = make_float2(v00, v01);
            *(float2*)(out + (row0 + 8) * O + col0)  = make_float2(v10, v11);
            sp[nt * 2 + 0]  += v00 + v10;
            sp[nt * 2 + 1]  += v01 + v11;
            ssp[nt * 2 + 0] += v00 * v00 + v10 * v10;
            ssp[nt * 2 + 1] += v01 * v01 + v11 * v11;
        }
    }
    #pragma unroll
    for (int c = 0; c < 8; c++) {
        #pragma unroll
        for (int mask = 4; mask <= 16; mask <<= 1) {
            sp[c]  += __shfl_xor_sync(0xffffffffu, sp[c],  mask);
            ssp[c] += __shfl_xor_sync(0xffffffffu, ssp[c], mask);
        }
    }
    if (lane < 4) {
        #pragma unroll
        for (int nt = 0; nt < 4; nt++) {
            #pragma unroll
            for (int h = 0; h < 2; h++) {
                int col = colBase + wn * 32 + nt * 8 + 2 * lane + h;
                atomicAdd(&sumArr[col],   sp[nt * 2 + h]);
                atomicAdd(&sumsqArr[col], ssp[nt * 2 + h]);
            }
        }
    }
}

// ---------------------------------------------------------------------------
// final BN+ReLU + transpose [b][n][o] -> [b][o][n] into d_out (O = 128).
__global__ void output_kernel(const float* __restrict__ in, float* __restrict__ out) {
    __shared__ float t[32][33];
    const int b = blockIdx.z;
    const int n0 = blockIdx.x * 32, o0 = blockIdx.y * 32;
    const int tx = threadIdx.x, ty = threadIdx.y; // 32 x 8
    #pragma unroll
    for (int k = 0; k < 32; k += 8) {
        int o = o0 + tx;
        float v = in[((size_t)b * Np + n0 + ty + k) * 128 + o];
        t[ty + k][tx] = fmaxf(fmaf(v, g_scale[o], g_shift[o]), 0.f);
    }
    __syncthreads();
    #pragma unroll
    for (int k = 0; k < 32; k += 8)
        out[((size_t)b * 128 + o0 + ty + k) * Np + n0 + tx] = t[tx][ty + k];
}

// ---------------------------------------------------------------------------
extern "C" void kernel_launch(void* const* d_in, const int* in_sizes, int n_in,
                              void* d_out, int out_size) {
    const float* p   = (const float*)d_in[0];
    const float* q   = (const float*)d_in[1];
    const float* x   = (const float*)d_in[2];
    const float* w0  = (const float*)d_in[3];
    const float* b0  = (const float*)d_in[4];
    const float* g0  = (const float*)d_in[5];
    const float* be0 = (const float*)d_in[6];
    const float* w1  = (const float*)d_in[7];
    const float* b1  = (const float*)d_in[8];
    const float* g1  = (const float*)d_in[9];
    const float* be1 = (const float*)d_in[10];
    const float* w2  = (const float*)d_in[11];
    const float* b2  = (const float*)d_in[12];
    const float* g2  = (const float*)d_in[13];
    const float* be2 = (const float*)d_in[14];
    float* out = (float*)d_out;

    float *bufA, *bufB, *xT;
    int4* gIdx; float4* gWt;
    float *sum0, *sumsq0, *sum1, *sumsq1, *sum2, *sumsq2;
    cudaGetSymbolAddress((void**)&bufA, g_bufA);
    cudaGetSymbolAddress((void**)&bufB, g_bufB);
    cudaGetSymbolAddress((void**)&xT,  g_xT);
    cudaGetSymbolAddress((void**)&gIdx, g_idx);
    cudaGetSymbolAddress((void**)&gWt,  g_wt);
    cudaGetSymbolAddress((void**)&sum0, g_sum0);
    cudaGetSymbolAddress((void**)&sumsq0, g_sumsq0);
    cudaGetSymbolAddress((void**)&sum1, g_sum1);
    cudaGetSymbolAddress((void**)&sumsq1, g_sumsq1);
    cudaGetSymbolAddress((void**)&sum2, g_sum2);
    cudaGetSymbolAddress((void**)&sumsq2, g_sumsq2);

    const int Qfloats = Bb * Mp * 3;                    // 24576
    const int Hfloats = Bb * 128 * Np;                  // 8388608
    const int qoff = (out_size >= Qfloats + Hfloats) ? Qfloats : 0;

    cudaFuncSetAttribute(gemm_bf16x3_kernel<0>,
                         cudaFuncAttributeMaxDynamicSharedMemorySize, SMEM_GEMM_BYTES);
    cudaFuncSetAttribute(gemm_bf16x3_kernel<1>,
                         cudaFuncAttributeMaxDynamicSharedMemorySize, SMEM_GEMM_BYTES);

    zero_stats_kernel<<<1, 256>>>();
    transpose_x_kernel<<<dim3(Mp / 32, Cc / 32, Bb), dim3(32, 8)>>>(x, xT);
    knn_kernel<<<dim3(Bb, Np / 128), 256>>>(p, q, gIdx, gWt);

    // layer 0: A gathered from xT on the fly, out bufB (256 ch) — stats fused
    gemm_bf16x3_kernel<1><<<dim3(Rr / 64, 2), 256, SMEM_GEMM_BYTES>>>(
        xT, w0, b0, 0, bufB, 256, sum0, sumsq0, gIdx, gWt);
    bn_finalize_kernel<<<1, 256>>>(sum0, sumsq0, g0, be0, 256);

    // layer 1: in bufB (BN0+ReLU via g_scale/g_shift), out bufA (256 ch)
    gemm_bf16x3_kernel<0><<<dim3(Rr / 64, 2), 256, SMEM_GEMM_BYTES>>>(
        bufB, w1, b1, 1, bufA, 256, sum1, sumsq1, nullptr, nullptr);
    bn_finalize_kernel<<<1, 256>>>(sum1, sumsq1, g1, be1, 256);

    // layer 2: in bufA (BN1+ReLU via g_scale/g_shift), out bufB (128 ch)
    gemm_bf16x3_kernel<0><<<dim3(Rr / 64, 1), 256, SMEM_GEMM_BYTES>>>(
        bufA, w2, b2, 1, bufB, 128, sum2, sumsq2, nullptr, nullptr);
    bn_finalize_kernel<<<1, 256>>>(sum2, sumsq2, g2, be2, 128);

    // output: [q | BN2+ReLU(h) transposed to [B,128,N]]
    if (qoff)
        cudaMemcpyAsync(out, q, (size_t)Qfloats * sizeof(float),
                        cudaMemcpyDeviceToDevice);
    output_kernel<<<dim3(Np / 32, 4, Bb), dim3(32, 8)>>>(bufB, out + qoff);
}

// round 16
// speedup vs baseline: 1.0333x; 1.0333x over previous
#include <cuda_runtime.h>
#include <cstddef>
#include <cstdint>

// Problem constants
#define Bb 8
#define Np 8192
#define Mp 1024
#define Cc 256
#define Rr (Bb*Np)       // 65536 rows
#define BN_EPS 1e-5f

// Scratch (static __device__ — no allocations allowed)
__device__ float g_bufA[(size_t)Rr*Cc];     // 64 MB
__device__ float g_bufB[(size_t)Rr*Cc];     // 64 MB
__device__ float g_xT[(size_t)Bb*Mp*Cc];    // 8 MB
__device__ float g_sum0[Cc],  g_sumsq0[Cc];
__device__ float g_sum1[Cc],  g_sumsq1[Cc];
__device__ float g_sum2[Cc],  g_sumsq2[Cc];
__device__ float g_scale[Cc];
__device__ float g_shift[Cc];

// ---------------------------------------------------------------------------
__global__ void zero_stats_kernel() {
    int t = threadIdx.x;
    g_sum0[t] = 0.f; g_sumsq0[t] = 0.f;
    g_sum1[t] = 0.f; g_sumsq1[t] = 0.f;
    g_sum2[t] = 0.f; g_sumsq2[t] = 0.f;
}

// fold BN into per-channel affine from raw sums: one tiny launch per layer
__global__ void bn_finalize_kernel(const float* __restrict__ sum,
                                   const float* __restrict__ sumsq,
                                   const float* __restrict__ g,
                                   const float* __restrict__ beta, int O) {
    int t = threadIdx.x;
    if (t < O) {
        const float cnt = (float)Rr;
        float mu  = sum[t] / cnt;
        float var = fmaxf(sumsq[t] / cnt - mu * mu, 0.f);
        float sc  = rsqrtf(var + BN_EPS) * g[t];
        g_scale[t] = sc;
        g_shift[t] = beta[t] - mu * sc;
    }
}

// ---------------------------------------------------------------------------
// transpose x[b][c][m] -> xT[b][m][c]
__global__ void transpose_x_kernel(const float* __restrict__ x, float* __restrict__ xT) {
    __shared__ float t[32][33];
    int b = blockIdx.z;
    int m0 = blockIdx.x * 32, c0 = blockIdx.y * 32;
    int tx = threadIdx.x, ty = threadIdx.y; // 32 x 8
    const float* xb = x + (size_t)b * Cc * Mp;
    #pragma unroll
    for (int k = 0; k < 32; k += 8)
        t[ty + k][tx] = xb[(size_t)(c0 + ty + k) * Mp + m0 + tx];
    __syncthreads();
    float* ob = xT + (size_t)b * Mp * Cc;
    #pragma unroll
    for (int k = 0; k < 32; k += 8)
        ob[(size_t)(m0 + ty + k) * Cc + c0 + tx] = t[tx][ty + k];
}

// ---------------------------------------------------------------------------
// 3-NN + inverse-distance interpolation. Writes h0 in [b][n][c].
// 512 threads, 128 points/block: 4 threads split each point's 1024-scan
// (256 each, even/odd ILP chains, 3-FMA inner loop via h=-2q precompute),
// ordered smem merge; gather with 16 warps x 8 points (float4).
__global__ void __launch_bounds__(512)
knn_interp_kernel(const float* __restrict__ p,
                  const float* __restrict__ q,
                  const float* __restrict__ xT,
                  float* __restrict__ h0) {
    __shared__ float shx[Mp], shy[Mp], shz[Mp], sqq[Mp];
    __shared__ float sd[512][3];
    __shared__ int   sdi[512][3];
    __shared__ float sw[128][3];
    __shared__ int   si[128][3];
    const int b = blockIdx.x;
    const int n0 = blockIdx.y * 128;
    const int tid = threadIdx.x;       // 512

    for (int m = tid; m < Mp; m += 512) {
        float qx = q[((size_t)b * Mp + m) * 3 + 0];
        float qy = q[((size_t)b * Mp + m) * 3 + 1];
        float qz = q[((size_t)b * Mp + m) * 3 + 2];
        shx[m] = -2.f * qx; shy[m] = -2.f * qy; shz[m] = -2.f * qz;
        sqq[m] = qx * qx + qy * qy + qz * qz;
    }
    __syncthreads();

    const int pt = tid & 127;          // point index
    const int part = tid >> 7;         // scan quarter (0..3)
    const int n = n0 + pt;
    const float px = p[((size_t)b * Np + n) * 3 + 0];
    const float py = p[((size_t)b * Np + n) * 3 + 1];
    const float pz = p[((size_t)b * Np + n) * 3 + 2];
    const float pp = px * px + py * py + pz * pz;

    // d'(m) = sqq[m] - 2*dot = fma(px,hx, fma(py,hy, fma(pz,hz, sqq)))
    float e0 = 3.4e38f, e1 = 3.4e38f, e2 = 3.4e38f;
    int   ei0 = 0, ei1 = 0, ei2 = 0;
    float o0 = 3.4e38f, o1 = 3.4e38f, o2 = 3.4e38f;
    int   oi0 = 0, oi1 = 0, oi2 = 0;
    const int mBase = part * 256;
    #pragma unroll 2
    for (int m = mBase; m < mBase + 256; m += 2) {
        float dE = fmaf(px, shx[m],   fmaf(py, shy[m],   fmaf(pz, shz[m],   sqq[m])));
        float dO = fmaf(px, shx[m+1], fmaf(py, shy[m+1], fmaf(pz, shz[m+1], sqq[m+1])));
        if (dE < e2) {
            if (dE < e1) {
                e2 = e1; ei2 = ei1;
                if (dE < e0) { e1 = e0; ei1 = ei0; e0 = dE; ei0 = m; }
                else         { e1 = dE; ei1 = m; }
            } else { e2 = dE; ei2 = m; }
        }
        if (dO < o2) {
            if (dO < o1) {
                o2 = o1; oi2 = oi1;
                if (dO < o0) { o1 = o0; oi1 = oi0; o0 = dO; oi0 = m+1; }
                else         { o1 = dO; oi1 = m+1; }
            } else { o2 = dO; oi2 = m+1; }
        }
    }
    // merge odd into even (same part; odd indices > even at equal m-range start,
    // strict < keeps earlier index on ties)
    #pragma unroll
    for (int c = 0; c < 3; c++) {
        float d = (c == 0) ? o0 : (c == 1) ? o1 : o2;
        int   i = (c == 0) ? oi0 : (c == 1) ? oi1 : oi2;
        if (d < e2) {
            if (d < e1) {
                e2 = e1; ei2 = ei1;
                if (d < e0) { e1 = e0; ei1 = ei0; e0 = d; ei0 = i; }
                else        { e1 = d; ei1 = i; }
            } else { e2 = d; ei2 = i; }
        }
    }
    // layout: sd[pt + part*128]
    sd[part * 128 + pt][0] = e0;  sd[part * 128 + pt][1] = e1;  sd[part * 128 + pt][2] = e2;
    sdi[part * 128 + pt][0] = ei0; sdi[part * 128 + pt][1] = ei1; sdi[part * 128 + pt][2] = ei2;
    __syncthreads();

    if (tid < 128) {
        float m0 = sd[tid][0], m1 = sd[tid][1], m2 = sd[tid][2];
        int   j0 = sdi[tid][0], j1 = sdi[tid][1], j2 = sdi[tid][2];
        #pragma unroll
        for (int pr = 1; pr < 4; pr++) {
            #pragma unroll
            for (int c = 0; c < 3; c++) {
                float d = sd[pr * 128 + tid][c];
                int   i = sdi[pr * 128 + tid][c];
                if (d < m2) {
                    if (d < m1) {
                        m2 = m1; j2 = j1;
                        if (d < m0) { m1 = m0; j1 = j0; m0 = d; j0 = i; }
                        else        { m1 = d; j1 = i; }
                    } else { m2 = d; j2 = i; }
                }
            }
        }
        float a0 = 1.f / fmaxf(m0 + pp, 1e-10f);
        float a1 = 1.f / fmaxf(m1 + pp, 1e-10f);
        float a2 = 1.f / fmaxf(m2 + pp, 1e-10f);
        float inv = 1.f / (a0 + a1 + a2);
        sw[tid][0] = a0 * inv; sw[tid][1] = a1 * inv; sw[tid][2] = a2 * inv;
        si[tid][0] = j0; si[tid][1] = j1; si[tid][2] = j2;
    }
    __syncthreads();

    const int lane = tid & 31, warp = tid >> 5;   // 16 warps x 8 points
    const float* xb = xT + (size_t)b * Mp * Cc;
    for (int nl = warp * 8; nl < warp * 8 + 8; nl++) {
        float w0 = sw[nl][0], w1 = sw[nl][1], w2 = sw[nl][2];
        const float4* r0 = (const float4*)(xb + (size_t)si[nl][0] * Cc);
        const float4* r1 = (const float4*)(xb + (size_t)si[nl][1] * Cc);
        const float4* r2 = (const float4*)(xb + (size_t)si[nl][2] * Cc);
        float4* o4 = (float4*)(h0 + ((size_t)b * Np + n0 + nl) * Cc);
        #pragma unroll
        for (int c = lane; c < Cc / 4; c += 32) {
            float4 a = r0[c], bq = r1[c], cq = r2[c];
            float4 v;
            v.x = w0 * a.x + w1 * bq.x + w2 * cq.x;
            v.y = w0 * a.y + w1 * bq.y + w2 * cq.y;
            v.z = w0 * a.z + w1 * bq.z + w2 * cq.z;
            v.w = w0 * a.w + w1 * bq.w + w2 * cq.w;
            o4[c] = v;
        }
    }
}

// ---------------------------------------------------------------------------
// bf16x3 emulated-fp32 GEMM via legacy mma.sync (sm_80 PTX path)
// ---------------------------------------------------------------------------
__device__ __forceinline__ uint32_t prmt_hi(uint32_t a, uint32_t b) {
    uint32_t r; asm("prmt.b32 %0, %1, %2, 0x7632;" : "=r"(r) : "r"(a), "r"(b));
    return r;   // {lo16 = a.hi16, hi16 = b.hi16}
}
__device__ __forceinline__ uint32_t pack_bf16_rn(float lo0, float lo1) {
    uint32_t r; asm("cvt.rn.bf16x2.f32 %0, %1, %2;" : "=r"(r) : "f"(lo1), "f"(lo0));
    return r;   // low half = lo0
}
__device__ __forceinline__ float trunc_hi_f(float f) {
    return __uint_as_float(__float_as_uint(f) & 0xFFFF0000u);
}

#define MMA_BF16(c, a, b0v, b1v) \
    asm volatile("mma.sync.aligned.m16n8k16.row.col.f32.bf16.bf16.f32 " \
        "{%0,%1,%2,%3},{%4,%5,%6,%7},{%8,%9},{%0,%1,%2,%3};" \
        : "+f"((c)[0]), "+f"((c)[1]), "+f"((c)[2]), "+f"((c)[3]) \
        : "r"((a).x), "r"((a).y), "r"((a).z), "r"((a).w), "r"(b0v), "r"(b1v))

#define LDMATRIX_X4(r, addr) \
    asm volatile("ldmatrix.sync.aligned.m8n8.x4.shared.b16 {%0,%1,%2,%3}, [%4];" \
        : "=r"((r).x), "=r"((r).y), "=r"((r).z), "=r"((r).w) : "r"(addr))

// smem tiles: bf16, row-major, rows x 32 k = 64 B/row, XOR-granule swizzle.
// Stage layout: A_hi(4K) A_lo(4K) B_hi(8K) B_lo(8K) = 24 KB; 4 stages = 96 KB.
#define A_TILE   4096
#define B_TILE   8192
#define STAGE_B  (2 * A_TILE + 2 * B_TILE)   // 24576
#define SMEM_GEMM_BYTES (4 * STAGE_B)        // 98304

// out[r][o] = sum_c act(A[r][c]) * W[o][c] + bias[o], K=256, CTA tile 64x128.
// 256 threads, 8 warps (2M x 4N), 2 CTAs/SM, 4-stage ring, barrier per 2 kb.
// Prev-layer BN+ReLU applied from precomputed g_scale/g_shift;
// BN stats fused into epilogue (per-layer arrays).
__global__ void __launch_bounds__(256, 2)
gemm_bf16x3_kernel(const float* __restrict__ A, const float* __restrict__ W,
                   const float* __restrict__ bias, int useAct,
                   float* __restrict__ out, int O,
                   float* __restrict__ sumArr, float* __restrict__ sumsqArr) {
    extern __shared__ char smc[];
    const int tid = threadIdx.x;
    const int lane = tid & 31, wid = tid >> 5;
    const int wm = wid >> 2, wn = wid & 3;           // 2M x 4N
    const size_t rowBase = (size_t)blockIdx.x * 64;
    const int colBase = blockIdx.y * 128;

    const uint32_t smb = (uint32_t)__cvta_generic_to_shared(smc);

    // producer mapping: prow = tid>>2 (0..63), pkg = tid&3 (8 k each)
    const int prow = tid >> 2;
    const int pkg = tid & 3;
    const uint32_t swz = (uint32_t)((pkg ^ ((prow >> 1) & 3)) << 4);
    const uint32_t aSlot  = (uint32_t)(prow * 64) + swz;
    const uint32_t bSlot0 = (uint32_t)(prow * 64) + swz;
    const uint32_t bSlot1 = (uint32_t)((prow + 64) * 64) +
                            (uint32_t)((pkg ^ (((prow + 64) >> 1) & 3)) << 4);
    const float* aG = A + (rowBase + prow) * 256 + pkg * 8;
    const float* wG0 = W + (size_t)(colBase + prow) * 256 + pkg * 8;
    const float* wG1 = W + (size_t)(colBase + prow + 64) * 256 + pkg * 8;

    float acc[2][4][4];
    #pragma unroll
    for (int i = 0; i < 2; i++)
        #pragma unroll
        for (int j = 0; j < 4; j++)
            #pragma unroll
            for (int r = 0; r < 4; r++) acc[i][j][r] = 0.f;

    float4 va0, va1, vb0, vb1, vb2, vb3;
    auto loadG = [&](int kb) {
        va0 = *(const float4*)(aG + kb * 32);
        va1 = *(const float4*)(aG + kb * 32 + 4);
        vb0 = *(const float4*)(wG0 + kb * 32);
        vb1 = *(const float4*)(wG0 + kb * 32 + 4);
        vb2 = *(const float4*)(wG1 + kb * 32);
        vb3 = *(const float4*)(wG1 + kb * 32 + 4);
    };
    auto cvt8 = [&](const float* a, uint4& hi, uint4& lo) {
        hi.x = prmt_hi(__float_as_uint(a[0]), __float_as_uint(a[1]));
        hi.y = prmt_hi(__float_as_uint(a[2]), __float_as_uint(a[3]));
        hi.z = prmt_hi(__float_as_uint(a[4]), __float_as_uint(a[5]));
        hi.w = prmt_hi(__float_as_uint(a[6]), __float_as_uint(a[7]));
        lo.x = pack_bf16_rn(a[0] - trunc_hi_f(a[0]), a[1] - trunc_hi_f(a[1]));
        lo.y = pack_bf16_rn(a[2] - trunc_hi_f(a[2]), a[3] - trunc_hi_f(a[3]));
        lo.z = pack_bf16_rn(a[4] - trunc_hi_f(a[4]), a[5] - trunc_hi_f(a[5]));
        lo.w = pack_bf16_rn(a[6] - trunc_hi_f(a[6]), a[7] - trunc_hi_f(a[7]));
    };
    auto storeS = [&](int s, int kb) {
        const uint32_t stg = smb + s * STAGE_B;
        float a[8] = {va0.x, va0.y, va0.z, va0.w, va1.x, va1.y, va1.z, va1.w};
        if (useAct) {
            int c = kb * 32 + pkg * 8;
            #pragma unroll
            for (int j = 0; j < 8; j++)
                a[j] = fmaxf(fmaf(a[j], g_scale[c + j], g_shift[c + j]), 0.f);
        }
        uint4 hi, lo;
        cvt8(a, hi, lo);
        asm volatile("st.shared.v4.b32 [%0], {%1,%2,%3,%4};"
                     :: "r"(stg + aSlot), "r"(hi.x), "r"(hi.y), "r"(hi.z), "r"(hi.w));
        asm volatile("st.shared.v4.b32 [%0], {%1,%2,%3,%4};"
                     :: "r"(stg + A_TILE + aSlot), "r"(lo.x), "r"(lo.y), "r"(lo.z), "r"(lo.w));

        float b0a[8] = {vb0.x, vb0.y, vb0.z, vb0.w, vb1.x, vb1.y, vb1.z, vb1.w};
        cvt8(b0a, hi, lo);
        asm volatile("st.shared.v4.b32 [%0], {%1,%2,%3,%4};"
                     :: "r"(stg + 2 * A_TILE + bSlot0), "r"(hi.x), "r"(hi.y), "r"(hi.z), "r"(hi.w));
        asm volatile("st.shared.v4.b32 [%0], {%1,%2,%3,%4};"
                     :: "r"(stg + 2 * A_TILE + B_TILE + bSlot0), "r"(lo.x), "r"(lo.y), "r"(lo.z), "r"(lo.w));

        float b1a[8] = {vb2.x, vb2.y, vb2.z, vb2.w, vb3.x, vb3.y, vb3.z, vb3.w};
        cvt8(b1a, hi, lo);
        asm volatile("st.shared.v4.b32 [%0], {%1,%2,%3,%4};"
                     :: "r"(stg + 2 * A_TILE + bSlot1), "r"(hi.x), "r"(hi.y), "r"(hi.z), "r"(hi.w));
        asm volatile("st.shared.v4.b32 [%0], {%1,%2,%3,%4};"
                     :: "r"(stg + 2 * A_TILE + B_TILE + bSlot1), "r"(lo.x), "r"(lo.y), "r"(lo.z), "r"(lo.w));
    };

    const int aRow0 = wm * 32 + ((lane >> 3) & 1) * 8 + (lane & 7);
    const int aKh = (lane >> 4) & 1;
    const int bRow0 = wn * 32 + ((lane >> 4) & 1) * 8 + (lane & 7);
    const int bKh = (lane >> 3) & 1;
    uint32_t aOff[2][2], bOff[2][2];
    #pragma unroll
    for (int mt = 0; mt < 2; mt++) {
        int row = aRow0 + mt * 16;
        #pragma unroll
        for (int ks = 0; ks < 2; ks++)
            aOff[mt][ks] = (uint32_t)(row * 64 + ((((ks << 1) + aKh) ^ ((row >> 1) & 3)) << 4));
    }
    #pragma unroll
    for (int p = 0; p < 2; p++) {
        int row = bRow0 + p * 16;
        #pragma unroll
        for (int ks = 0; ks < 2; ks++)
            bOff[p][ks] = (uint32_t)(2 * A_TILE + row * 64 + ((((ks << 1) + bKh) ^ ((row >> 1) & 3)) << 4));
    }

    auto consume = [&](int s) {
        const uint32_t stg = smb + s * STAGE_B;
        uint4 ah[2], al[2], bh[2][2], bl[2][2];
        #pragma unroll
        for (int mt = 0; mt < 2; mt++) {
            LDMATRIX_X4(ah[mt], stg + aOff[mt][0]);
            LDMATRIX_X4(al[mt], stg + aOff[mt][0] + A_TILE);
        }
        #pragma unroll
        for (int p = 0; p < 2; p++) {
            LDMATRIX_X4(bh[0][p], stg + bOff[p][0]);
            LDMATRIX_X4(bl[0][p], stg + bOff[p][0] + B_TILE);
        }
        #pragma unroll
        for (int p = 0; p < 2; p++) {
            LDMATRIX_X4(bh[1][p], stg + bOff[p][1]);
            LDMATRIX_X4(bl[1][p], stg + bOff[p][1] + B_TILE);
        }
        #pragma unroll
        for (int mt = 0; mt < 2; mt++) {
            #pragma unroll
            for (int p = 0; p < 2; p++) {
                MMA_BF16(acc[mt][2*p],   ah[mt], bh[0][p].x, bh[0][p].y);
                MMA_BF16(acc[mt][2*p],   ah[mt], bl[0][p].x, bl[0][p].y);
                MMA_BF16(acc[mt][2*p],   al[mt], bh[0][p].x, bh[0][p].y);
                MMA_BF16(acc[mt][2*p+1], ah[mt], bh[0][p].z, bh[0][p].w);
                MMA_BF16(acc[mt][2*p+1], ah[mt], bl[0][p].z, bl[0][p].w);
                MMA_BF16(acc[mt][2*p+1], al[mt], bh[0][p].z, bh[0][p].w);
            }
        }
        #pragma unroll
        for (int mt = 0; mt < 2; mt++) {
            LDMATRIX_X4(ah[mt], stg + aOff[mt][1]);
            LDMATRIX_X4(al[mt], stg + aOff[mt][1] + A_TILE);
        }
        #pragma unroll
        for (int mt = 0; mt < 2; mt++) {
            #pragma unroll
            for (int p = 0; p < 2; p++) {
                MMA_BF16(acc[mt][2*p],   ah[mt], bh[1][p].x, bh[1][p].y);
                MMA_BF16(acc[mt][2*p],   ah[mt], bl[1][p].x, bl[1][p].y);
                MMA_BF16(acc[mt][2*p],   al[mt], bh[1][p].x, bh[1][p].y);
                MMA_BF16(acc[mt][2*p+1], ah[mt], bh[1][p].z, bh[1][p].w);
                MMA_BF16(acc[mt][2*p+1], ah[mt], bl[1][p].z, bl[1][p].w);
                MMA_BF16(acc[mt][2*p+1], al[mt], bh[1][p].z, bh[1][p].w);
            }
        }
    };

    // prologue
    loadG(0); storeS(0, 0);
    loadG(1); storeS(1, 1);
    __syncthreads();

    // mainloop: one barrier per 2 K-blocks
    #pragma unroll 1
    for (int kbp = 0; kbp < 8; kbp += 2) {
        if (kbp + 2 < 8) loadG(kbp + 2);
        consume(kbp & 3);
        if (kbp + 2 < 8) storeS((kbp + 2) & 3, kbp + 2);
        if (kbp + 3 < 8) loadG(kbp + 3);
        consume((kbp + 1) & 3);
        if (kbp + 3 < 8) storeS((kbp + 3) & 3, kbp + 3);
        if (kbp + 2 < 8) __syncthreads();
    }

    // epilogue: +bias, store, fused per-channel stats
    float sp[8], ssp[8];
    #pragma unroll
    for (int c = 0; c < 8; c++) { sp[c] = 0.f; ssp[c] = 0.f; }

    const int gId = lane >> 2, l4 = lane & 3;
    #pragma unroll
    for (int mt = 0; mt < 2; mt++) {
        size_t row0 = rowBase + wm * 32 + mt * 16 + gId;
        #pragma unroll
        for (int nt = 0; nt < 4; nt++) {
            int col0 = colBase + wn * 32 + nt * 8 + 2 * l4;
            float b0 = bias[col0], b1 = bias[col0 + 1];
            float v00 = acc[mt][nt][0] + b0, v01 = acc[mt][nt][1] + b1;
            float v10 = acc[mt][nt][2] + b0, v11 = acc[mt][nt][3] + b1;
            *(float2*)(out + row0 * O + col0)        = make_float2(v00, v01);
            *(float2*)(out + (row0 + 8) * O + col0)  = make_float2(v10, v11);
            sp[nt * 2 + 0]  += v00 + v10;
            sp[nt * 2 + 1]  += v01 + v11;
            ssp[nt * 2 + 0] += v00 * v00 + v10 * v10;
            ssp[nt * 2 + 1] += v01 * v01 + v11 * v11;
        }
    }
    #pragma unroll
    for (int c = 0; c < 8; c++) {
        #pragma unroll
        for (int mask = 4; mask <= 16; mask <<= 1) {
            sp[c]  += __shfl_xor_sync(0xffffffffu, sp[c],  mask);
            ssp[c] += __shfl_xor_sync(0xffffffffu, ssp[c], mask);
        }
    }
    if (lane < 4) {
        #pragma unroll
        for (int nt = 0; nt < 4; nt++) {
            #pragma unroll
            for (int h = 0; h < 2; h++) {
                int col = colBase + wn * 32 + nt * 8 + 2 * lane + h;
                atomicAdd(&sumArr[col],   sp[nt * 2 + h]);
                atomicAdd(&sumsqArr[col], ssp[nt * 2 + h]);
            }
        }
    }
}

// ---------------------------------------------------------------------------
// final BN+ReLU + transpose [b][n][o] -> [b][o][n] into d_out (O = 128).
__global__ void output_kernel(const float* __restrict__ in, float* __restrict__ out) {
    __shared__ float t[32][33];
    const int b = blockIdx.z;
    const int n0 = blockIdx.x * 32, o0 = blockIdx.y * 32;
    const int tx = threadIdx.x, ty = threadIdx.y; // 32 x 8
    #pragma unroll
    for (int k = 0; k < 32; k += 8) {
        int o = o0 + tx;
        float v = in[((size_t)b * Np + n0 + ty + k) * 128 + o];
        t[ty + k][tx] = fmaxf(fmaf(v, g_scale[o], g_shift[o]), 0.f);
    }
    __syncthreads();
    #pragma unroll
    for (int k = 0; k < 32; k += 8)
        out[((size_t)b * 128 + o0 + ty + k) * Np + n0 + tx] = t[tx][ty + k];
}

// ---------------------------------------------------------------------------
extern "C" void kernel_launch(void* const* d_in, const int* in_sizes, int n_in,
                              void* d_out, int out_size) {
    const float* p   = (const float*)d_in[0];
    const float* q   = (const float*)d_in[1];
    const float* x   = (const float*)d_in[2];
    const float* w0  = (const float*)d_in[3];
    const float* b0  = (const float*)d_in[4];
    const float* g0  = (const float*)d_in[5];
    const float* be0 = (const float*)d_in[6];
    const float* w1  = (const float*)d_in[7];
    const float* b1  = (const float*)d_in[8];
    const float* g1  = (const float*)d_in[9];
    const float* be1 = (const float*)d_in[10];
    const float* w2  = (const float*)d_in[11];
    const float* b2  = (const float*)d_in[12];
    const float* g2  = (const float*)d_in[13];
    const float* be2 = (const float*)d_in[14];
    float* out = (float*)d_out;

    float *bufA, *bufB, *xT;
    float *sum0, *sumsq0, *sum1, *sumsq1, *sum2, *sumsq2;
    cudaGetSymbolAddress((void**)&bufA, g_bufA);
    cudaGetSymbolAddress((void**)&bufB, g_bufB);
    cudaGetSymbolAddress((void**)&xT,  g_xT);
    cudaGetSymbolAddress((void**)&sum0, g_sum0);
    cudaGetSymbolAddress((void**)&sumsq0, g_sumsq0);
    cudaGetSymbolAddress((void**)&sum1, g_sum1);
    cudaGetSymbolAddress((void**)&sumsq1, g_sumsq1);
    cudaGetSymbolAddress((void**)&sum2, g_sum2);
    cudaGetSymbolAddress((void**)&sumsq2, g_sumsq2);

    const int Qfloats = Bb * Mp * 3;                    // 24576
    const int Hfloats = Bb * 128 * Np;                  // 8388608
    const int qoff = (out_size >= Qfloats + Hfloats) ? Qfloats : 0;

    cudaFuncSetAttribute(gemm_bf16x3_kernel,
                         cudaFuncAttributeMaxDynamicSharedMemorySize, SMEM_GEMM_BYTES);

    zero_stats_kernel<<<1, 256>>>();
    transpose_x_kernel<<<dim3(Mp / 32, Cc / 32, Bb), dim3(32, 8)>>>(x, xT);
    knn_interp_kernel<<<dim3(Bb, Np / 128), 512>>>(p, q, xT, bufA);

    // layer 0: in bufA (raw), out bufB (256 ch) — stats fused
    gemm_bf16x3_kernel<<<dim3(Rr / 64, 2), 256, SMEM_GEMM_BYTES>>>(
        bufA, w0, b0, 0, bufB, 256, sum0, sumsq0);
    bn_finalize_kernel<<<1, 256>>>(sum0, sumsq0, g0, be0, 256);

    // layer 1: in bufB (BN0+ReLU via g_scale/g_shift), out bufA (256 ch)
    gemm_bf16x3_kernel<<<dim3(Rr / 64, 2), 256, SMEM_GEMM_BYTES>>>(
        bufB, w1, b1, 1, bufA, 256, sum1, sumsq1);
    bn_finalize_kernel<<<1, 256>>>(sum1, sumsq1, g1, be1, 256);

    // layer 2: in bufA (BN1+ReLU via g_scale/g_shift), out bufB (128 ch)
    gemm_bf16x3_kernel<<<dim3(Rr / 64, 1), 256, SMEM_GEMM_BYTES>>>(
        bufA, w2, b2, 1, bufB, 128, sum2, sumsq2);
    bn_finalize_kernel<<<1, 256>>>(sum2, sumsq2, g2, be2, 128);

    // output: [q | BN2+ReLU(h) transposed to [B,128,N]]
    if (qoff)
        cudaMemcpyAsync(out, q, (size_t)Qfloats * sizeof(float),
                        cudaMemcpyDeviceToDevice);
    output_kernel<<<dim3(Np / 32, 4, Bb), dim3(32, 8)>>>(bufB, out + qoff);
}

// round 17
// speedup vs baseline: 1.0874x; 1.0523x over previous
#include <cuda_runtime.h>
#include <cstddef>
#include <cstdint>

// Problem constants
#define Bb 8
#define Np 8192
#define Mp 1024
#define Cc 256
#define Rr (Bb*Np)       // 65536 rows
#define BN_EPS 1e-5f

// Scratch (static __device__ — no allocations allowed)
__device__ float g_bufA[(size_t)Rr*Cc];     // 64 MB
__device__ float g_bufB[(size_t)Rr*Cc];     // 64 MB
__device__ float g_xT[(size_t)Bb*Mp*Cc];    // 8 MB
__device__ uint4 g_wcv[40960];              // 640 KB: w0(16)+w1(16)+w2(8) chunks of 16KB
__device__ float g_sum0[Cc],  g_sumsq0[Cc];
__device__ float g_sum1[Cc],  g_sumsq1[Cc];
__device__ float g_sum2[Cc],  g_sumsq2[Cc];
__device__ float g_scale[Cc];
__device__ float g_shift[Cc];

// ---------------------------------------------------------------------------
__global__ void zero_stats_kernel() {
    int t = threadIdx.x;
    g_sum0[t] = 0.f; g_sumsq0[t] = 0.f;
    g_sum1[t] = 0.f; g_sumsq1[t] = 0.f;
    g_sum2[t] = 0.f; g_sumsq2[t] = 0.f;
}

// fold BN into per-channel affine from raw sums: one tiny launch per layer
__global__ void bn_finalize_kernel(const float* __restrict__ sum,
                                   const float* __restrict__ sumsq,
                                   const float* __restrict__ g,
                                   const float* __restrict__ beta, int O) {
    int t = threadIdx.x;
    if (t < O) {
        const float cnt = (float)Rr;
        float mu  = sum[t] / cnt;
        float var = fmaxf(sumsq[t] / cnt - mu * mu, 0.f);
        float sc  = rsqrtf(var + BN_EPS) * g[t];
        g_scale[t] = sc;
        g_shift[t] = beta[t] - mu * sc;
    }
}

// ---------------------------------------------------------------------------
// transpose x[b][c][m] -> xT[b][m][c]
__global__ void transpose_x_kernel(const float* __restrict__ x, float* __restrict__ xT) {
    __shared__ float t[32][33];
    int b = blockIdx.z;
    int m0 = blockIdx.x * 32, c0 = blockIdx.y * 32;
    int tx = threadIdx.x, ty = threadIdx.y; // 32 x 8
    const float* xb = x + (size_t)b * Cc * Mp;
    #pragma unroll
    for (int k = 0; k < 32; k += 8)
        t[ty + k][tx] = xb[(size_t)(c0 + ty + k) * Mp + m0 + tx];
    __syncthreads();
    float* ob = xT + (size_t)b * Mp * Cc;
    #pragma unroll
    for (int k = 0; k < 32; k += 8)
        ob[(size_t)(m0 + ty + k) * Cc + c0 + tx] = t[tx][ty + k];
}

// ---------------------------------------------------------------------------
// bf16x3 helpers
// ---------------------------------------------------------------------------
__device__ __forceinline__ uint32_t prmt_hi(uint32_t a, uint32_t b) {
    uint32_t r; asm("prmt.b32 %0, %1, %2, 0x7632;" : "=r"(r) : "r"(a), "r"(b));
    return r;   // {lo16 = a.hi16, hi16 = b.hi16}
}
__device__ __forceinline__ uint32_t pack_bf16_rn(float lo0, float lo1) {
    uint32_t r; asm("cvt.rn.bf16x2.f32 %0, %1, %2;" : "=r"(r) : "f"(lo1), "f"(lo0));
    return r;   // low half = lo0
}
__device__ __forceinline__ float trunc_hi_f(float f) {
    return __uint_as_float(__float_as_uint(f) & 0xFFFF0000u);
}

// ---------------------------------------------------------------------------
// W pre-convert: one launch, all 3 layers -> swizzled hi/lo stage images.
// chunk = 16 KB: [hi tile 8 KB | lo tile 8 KB]; 512 threads, one granule each.
// chunks 0..15: w0 (nb=c>>3, kb=c&7); 16..31: w1; 32..39: w2 (nb=0).
__global__ void wconv_kernel(const float* __restrict__ w0,
                             const float* __restrict__ w1,
                             const float* __restrict__ w2,
                             uint4* __restrict__ wcv) {
    const int chunk = blockIdx.x;
    const float* W; int nb, kb;
    if (chunk < 16)      { W = w0; nb = chunk >> 3;        kb = chunk & 7; }
    else if (chunk < 32) { W = w1; nb = (chunk - 16) >> 3; kb = chunk & 7; }
    else                 { W = w2; nb = 0;                 kb = chunk & 7; }
    const int tid = threadIdx.x;          // 512
    const int r = tid >> 2;               // row within 128
    const int c16 = tid & 3;              // granule position within row
    const int kg = c16 ^ ((r >> 1) & 3);  // inverse swizzle -> logical granule
    const float* src = W + (size_t)(nb * 128 + r) * 256 + kb * 32 + kg * 8;
    float4 v0 = *(const float4*)src;
    float4 v1 = *(const float4*)(src + 4);
    float a[8] = {v0.x, v0.y, v0.z, v0.w, v1.x, v1.y, v1.z, v1.w};
    uint4 hi, lo;
    hi.x = prmt_hi(__float_as_uint(a[0]), __float_as_uint(a[1]));
    hi.y = prmt_hi(__float_as_uint(a[2]), __float_as_uint(a[3]));
    hi.z = prmt_hi(__float_as_uint(a[4]), __float_as_uint(a[5]));
    hi.w = prmt_hi(__float_as_uint(a[6]), __float_as_uint(a[7]));
    lo.x = pack_bf16_rn(a[0] - trunc_hi_f(a[0]), a[1] - trunc_hi_f(a[1]));
    lo.y = pack_bf16_rn(a[2] - trunc_hi_f(a[2]), a[3] - trunc_hi_f(a[3]));
    lo.z = pack_bf16_rn(a[4] - trunc_hi_f(a[4]), a[5] - trunc_hi_f(a[5]));
    lo.w = pack_bf16_rn(a[6] - trunc_hi_f(a[6]), a[7] - trunc_hi_f(a[7]));
    const size_t base = (size_t)chunk * 1024;
    wcv[base + tid]       = hi;
    wcv[base + 512 + tid] = lo;
}

// ---------------------------------------------------------------------------
// 3-NN + inverse-distance interpolation. Writes h0 in [b][n][c].
// 512 threads, 128 points/block: 4 threads split each point's 1024-scan
// (256 each, even/odd ILP chains, 3-FMA inner loop via h=-2q precompute),
// ordered smem merge; gather with 16 warps x 8 points (float4).
__global__ void __launch_bounds__(512)
knn_interp_kernel(const float* __restrict__ p,
                  const float* __restrict__ q,
                  const float* __restrict__ xT,
                  float* __restrict__ h0) {
    __shared__ float shx[Mp], shy[Mp], shz[Mp], sqq[Mp];
    __shared__ float sd[512][3];
    __shared__ int   sdi[512][3];
    __shared__ float sw[128][3];
    __shared__ int   si[128][3];
    const int b = blockIdx.x;
    const int n0 = blockIdx.y * 128;
    const int tid = threadIdx.x;       // 512

    for (int m = tid; m < Mp; m += 512) {
        float qx = q[((size_t)b * Mp + m) * 3 + 0];
        float qy = q[((size_t)b * Mp + m) * 3 + 1];
        float qz = q[((size_t)b * Mp + m) * 3 + 2];
        shx[m] = -2.f * qx; shy[m] = -2.f * qy; shz[m] = -2.f * qz;
        sqq[m] = qx * qx + qy * qy + qz * qz;
    }
    __syncthreads();

    const int pt = tid & 127;          // point index
    const int part = tid >> 7;         // scan quarter (0..3)
    const int n = n0 + pt;
    const float px = p[((size_t)b * Np + n) * 3 + 0];
    const float py = p[((size_t)b * Np + n) * 3 + 1];
    const float pz = p[((size_t)b * Np + n) * 3 + 2];
    const float pp = px * px + py * py + pz * pz;

    float e0 = 3.4e38f, e1 = 3.4e38f, e2 = 3.4e38f;
    int   ei0 = 0, ei1 = 0, ei2 = 0;
    float o0 = 3.4e38f, o1 = 3.4e38f, o2 = 3.4e38f;
    int   oi0 = 0, oi1 = 0, oi2 = 0;
    const int mBase = part * 256;
    #pragma unroll 2
    for (int m = mBase; m < mBase + 256; m += 2) {
        float dE = fmaf(px, shx[m],   fmaf(py, shy[m],   fmaf(pz, shz[m],   sqq[m])));
        float dO = fmaf(px, shx[m+1], fmaf(py, shy[m+1], fmaf(pz, shz[m+1], sqq[m+1])));
        if (dE < e2) {
            if (dE < e1) {
                e2 = e1; ei2 = ei1;
                if (dE < e0) { e1 = e0; ei1 = ei0; e0 = dE; ei0 = m; }
                else         { e1 = dE; ei1 = m; }
            } else { e2 = dE; ei2 = m; }
        }
        if (dO < o2) {
            if (dO < o1) {
                o2 = o1; oi2 = oi1;
                if (dO < o0) { o1 = o0; oi1 = oi0; o0 = dO; oi0 = m+1; }
                else         { o1 = dO; oi1 = m+1; }
            } else { o2 = dO; oi2 = m+1; }
        }
    }
    #pragma unroll
    for (int c = 0; c < 3; c++) {
        float d = (c == 0) ? o0 : (c == 1) ? o1 : o2;
        int   i = (c == 0) ? oi0 : (c == 1) ? oi1 : oi2;
        if (d < e2) {
            if (d < e1) {
                e2 = e1; ei2 = ei1;
                if (d < e0) { e1 = e0; ei1 = ei0; e0 = d; ei0 = i; }
                else        { e1 = d; ei1 = i; }
            } else { e2 = d; ei2 = i; }
        }
    }
    sd[part * 128 + pt][0] = e0;  sd[part * 128 + pt][1] = e1;  sd[part * 128 + pt][2] = e2;
    sdi[part * 128 + pt][0] = ei0; sdi[part * 128 + pt][1] = ei1; sdi[part * 128 + pt][2] = ei2;
    __syncthreads();

    if (tid < 128) {
        float m0 = sd[tid][0], m1 = sd[tid][1], m2 = sd[tid][2];
        int   j0 = sdi[tid][0], j1 = sdi[tid][1], j2 = sdi[tid][2];
        #pragma unroll
        for (int pr = 1; pr < 4; pr++) {
            #pragma unroll
            for (int c = 0; c < 3; c++) {
                float d = sd[pr * 128 + tid][c];
                int   i = sdi[pr * 128 + tid][c];
                if (d < m2) {
                    if (d < m1) {
                        m2 = m1; j2 = j1;
                        if (d < m0) { m1 = m0; j1 = j0; m0 = d; j0 = i; }
                        else        { m1 = d; j1 = i; }
                    } else { m2 = d; j2 = i; }
                }
            }
        }
        float a0 = 1.f / fmaxf(m0 + pp, 1e-10f);
        float a1 = 1.f / fmaxf(m1 + pp, 1e-10f);
        float a2 = 1.f / fmaxf(m2 + pp, 1e-10f);
        float inv = 1.f / (a0 + a1 + a2);
        sw[tid][0] = a0 * inv; sw[tid][1] = a1 * inv; sw[tid][2] = a2 * inv;
        si[tid][0] = j0; si[tid][1] = j1; si[tid][2] = j2;
    }
    __syncthreads();

    const int lane = tid & 31, warp = tid >> 5;   // 16 warps x 8 points
    const float* xb = xT + (size_t)b * Mp * Cc;
    for (int nl = warp * 8; nl < warp * 8 + 8; nl++) {
        float w0 = sw[nl][0], w1 = sw[nl][1], w2 = sw[nl][2];
        const float4* r0 = (const float4*)(xb + (size_t)si[nl][0] * Cc);
        const float4* r1 = (const float4*)(xb + (size_t)si[nl][1] * Cc);
        const float4* r2 = (const float4*)(xb + (size_t)si[nl][2] * Cc);
        float4* o4 = (float4*)(h0 + ((size_t)b * Np + n0 + nl) * Cc);
        #pragma unroll
        for (int c = lane; c < Cc / 4; c += 32) {
            float4 a = r0[c], bq = r1[c], cq = r2[c];
            float4 v;
            v.x = w0 * a.x + w1 * bq.x + w2 * cq.x;
            v.y = w0 * a.y + w1 * bq.y + w2 * cq.y;
            v.z = w0 * a.z + w1 * bq.z + w2 * cq.z;
            v.w = w0 * a.w + w1 * bq.w + w2 * cq.w;
            o4[c] = v;
        }
    }
}

// ---------------------------------------------------------------------------
#define MMA_BF16(c, a, b0v, b1v) \
    asm volatile("mma.sync.aligned.m16n8k16.row.col.f32.bf16.bf16.f32 " \
        "{%0,%1,%2,%3},{%4,%5,%6,%7},{%8,%9},{%0,%1,%2,%3};" \
        : "+f"((c)[0]), "+f"((c)[1]), "+f"((c)[2]), "+f"((c)[3]) \
        : "r"((a).x), "r"((a).y), "r"((a).z), "r"((a).w), "r"(b0v), "r"(b1v))

#define LDMATRIX_X4(r, addr) \
    asm volatile("ldmatrix.sync.aligned.m8n8.x4.shared.b16 {%0,%1,%2,%3}, [%4];" \
        : "=r"((r).x), "=r"((r).y), "=r"((r).z), "=r"((r).w) : "r"(addr))

// smem tiles: bf16, row-major, rows x 32 k = 64 B/row, XOR-granule swizzle.
// Stage layout: A_hi(4K) A_lo(4K) B_hi(8K) B_lo(8K) = 24 KB; 4 stages = 96 KB.
#define A_TILE   4096
#define B_TILE   8192
#define STAGE_B  (2 * A_TILE + 2 * B_TILE)   // 24576
#define SMEM_GEMM_BYTES (4 * STAGE_B)        // 98304

// out[r][o] = sum_c act(A[r][c]) * W[o][c] + bias[o], K=256, CTA tile 64x128.
// 256 threads, 8 warps (2M x 4N), 2 CTAs/SM, 4-stage ring, barrier per 2 kb.
// B tiles read PRE-CONVERTED (swizzled hi/lo image in wcv) — pure LDG+STS.
// Prev-layer BN+ReLU from g_scale/g_shift; BN stats fused into epilogue.
__global__ void __launch_bounds__(256, 2)
gemm_bf16x3_kernel(const float* __restrict__ A, const uint4* __restrict__ wcv,
                   const float* __restrict__ bias, int useAct,
                   float* __restrict__ out, int O,
                   float* __restrict__ sumArr, float* __restrict__ sumsqArr) {
    extern __shared__ char smc[];
    const int tid = threadIdx.x;
    const int lane = tid & 31, wid = tid >> 5;
    const int wm = wid >> 2, wn = wid & 3;           // 2M x 4N
    const size_t rowBase = (size_t)blockIdx.x * 64;
    const int colBase = blockIdx.y * 128;

    const uint32_t smb = (uint32_t)__cvta_generic_to_shared(smc);

    // producer mapping: prow = tid>>2 (0..63), pkg = tid&3 (8 k each)
    const int prow = tid >> 2;
    const int pkg = tid & 3;
    const uint32_t swz = (uint32_t)((pkg ^ ((prow >> 1) & 3)) << 4);
    const uint32_t aSlot  = (uint32_t)(prow * 64) + swz;
    const uint32_t bSlot0 = (uint32_t)(prow * 64) + swz;
    const uint32_t bSlot1 = (uint32_t)((prow + 64) * 64) +
                            (uint32_t)((pkg ^ (((prow + 64) >> 1) & 3)) << 4);
    const float* aG = A + (rowBase + prow) * 256 + pkg * 8;
    // pre-converted W: chunk (blockIdx.y*8 + kb) of 1024 granules; granule idx = byteoff>>4
    const uint4* wBase = wcv + (size_t)blockIdx.y * 8 * 1024;
    const uint32_t bG0 = bSlot0 >> 4, bG1 = bSlot1 >> 4;

    float acc[2][4][4];
    #pragma unroll
    for (int i = 0; i < 2; i++)
        #pragma unroll
        for (int j = 0; j < 4; j++)
            #pragma unroll
            for (int r = 0; r < 4; r++) acc[i][j][r] = 0.f;

    float4 va0, va1;
    uint4 wh0, wl0, wh1, wl1;
    auto loadG = [&](int kb) {
        va0 = *(const float4*)(aG + kb * 32);
        va1 = *(const float4*)(aG + kb * 32 + 4);
        const uint4* wc = wBase + (size_t)kb * 1024;
        wh0 = wc[bG0]; wl0 = wc[512 + bG0];
        wh1 = wc[bG1]; wl1 = wc[512 + bG1];
    };
    auto cvt8 = [&](const float* a, uint4& hi, uint4& lo) {
        hi.x = prmt_hi(__float_as_uint(a[0]), __float_as_uint(a[1]));
        hi.y = prmt_hi(__float_as_uint(a[2]), __float_as_uint(a[3]));
        hi.z = prmt_hi(__float_as_uint(a[4]), __float_as_uint(a[5]));
        hi.w = prmt_hi(__float_as_uint(a[6]), __float_as_uint(a[7]));
        lo.x = pack_bf16_rn(a[0] - trunc_hi_f(a[0]), a[1] - trunc_hi_f(a[1]));
        lo.y = pack_bf16_rn(a[2] - trunc_hi_f(a[2]), a[3] - trunc_hi_f(a[3]));
        lo.z = pack_bf16_rn(a[4] - trunc_hi_f(a[4]), a[5] - trunc_hi_f(a[5]));
        lo.w = pack_bf16_rn(a[6] - trunc_hi_f(a[6]), a[7] - trunc_hi_f(a[7]));
    };
    auto storeS = [&](int s, int kb) {
        const uint32_t stg = smb + s * STAGE_B;
        float a[8] = {va0.x, va0.y, va0.z, va0.w, va1.x, va1.y, va1.z, va1.w};
        if (useAct) {
            int c = kb * 32 + pkg * 8;
            #pragma unroll
            for (int j = 0; j < 8; j++)
                a[j] = fmaxf(fmaf(a[j], g_scale[c + j], g_shift[c + j]), 0.f);
        }
        uint4 hi, lo;
        cvt8(a, hi, lo);
        asm volatile("st.shared.v4.b32 [%0], {%1,%2,%3,%4};"
                     :: "r"(stg + aSlot), "r"(hi.x), "r"(hi.y), "r"(hi.z), "r"(hi.w));
        asm volatile("st.shared.v4.b32 [%0], {%1,%2,%3,%4};"
                     :: "r"(stg + A_TILE + aSlot), "r"(lo.x), "r"(lo.y), "r"(lo.z), "r"(lo.w));
        asm volatile("st.shared.v4.b32 [%0], {%1,%2,%3,%4};"
                     :: "r"(stg + 2 * A_TILE + bSlot0), "r"(wh0.x), "r"(wh0.y), "r"(wh0.z), "r"(wh0.w));
        asm volatile("st.shared.v4.b32 [%0], {%1,%2,%3,%4};"
                     :: "r"(stg + 2 * A_TILE + B_TILE + bSlot0), "r"(wl0.x), "r"(wl0.y), "r"(wl0.z), "r"(wl0.w));
        asm volatile("st.shared.v4.b32 [%0], {%1,%2,%3,%4};"
                     :: "r"(stg + 2 * A_TILE + bSlot1), "r"(wh1.x), "r"(wh1.y), "r"(wh1.z), "r"(wh1.w));
        asm volatile("st.shared.v4.b32 [%0], {%1,%2,%3,%4};"
                     :: "r"(stg + 2 * A_TILE + B_TILE + bSlot1), "r"(wl1.x), "r"(wl1.y), "r"(wl1.z), "r"(wl1.w));
    };

    const int aRow0 = wm * 32 + ((lane >> 3) & 1) * 8 + (lane & 7);
    const int aKh = (lane >> 4) & 1;
    const int bRow0 = wn * 32 + ((lane >> 4) & 1) * 8 + (lane & 7);
    const int bKh = (lane >> 3) & 1;
    uint32_t aOff[2][2], bOff[2][2];
    #pragma unroll
    for (int mt = 0; mt < 2; mt++) {
        int row = aRow0 + mt * 16;
        #pragma unroll
        for (int ks = 0; ks < 2; ks++)
            aOff[mt][ks] = (uint32_t)(row * 64 + ((((ks << 1) + aKh) ^ ((row >> 1) & 3)) << 4));
    }
    #pragma unroll
    for (int p = 0; p < 2; p++) {
        int row = bRow0 + p * 16;
        #pragma unroll
        for (int ks = 0; ks < 2; ks++)
            bOff[p][ks] = (uint32_t)(2 * A_TILE + row * 64 + ((((ks << 1) + bKh) ^ ((row >> 1) & 3)) << 4));
    }

    auto consume = [&](int s) {
        const uint32_t stg = smb + s * STAGE_B;
        uint4 ah[2], al[2], bh[2][2], bl[2][2];
        #pragma unroll
        for (int mt = 0; mt < 2; mt++) {
            LDMATRIX_X4(ah[mt], stg + aOff[mt][0]);
            LDMATRIX_X4(al[mt], stg + aOff[mt][0] + A_TILE);
        }
        #pragma unroll
        for (int p = 0; p < 2; p++) {
            LDMATRIX_X4(bh[0][p], stg + bOff[p][0]);
            LDMATRIX_X4(bl[0][p], stg + bOff[p][0] + B_TILE);
        }
        #pragma unroll
        for (int p = 0; p < 2; p++) {
            LDMATRIX_X4(bh[1][p], stg + bOff[p][1]);
            LDMATRIX_X4(bl[1][p], stg + bOff[p][1] + B_TILE);
        }
        #pragma unroll
        for (int mt = 0; mt < 2; mt++) {
            #pragma unroll
            for (int p = 0; p < 2; p++) {
                MMA_BF16(acc[mt][2*p],   ah[mt], bh[0][p].x, bh[0][p].y);
                MMA_BF16(acc[mt][2*p],   ah[mt], bl[0][p].x, bl[0][p].y);
                MMA_BF16(acc[mt][2*p],   al[mt], bh[0][p].x, bh[0][p].y);
                MMA_BF16(acc[mt][2*p+1], ah[mt], bh[0][p].z, bh[0][p].w);
                MMA_BF16(acc[mt][2*p+1], ah[mt], bl[0][p].z, bl[0][p].w);
                MMA_BF16(acc[mt][2*p+1], al[mt], bh[0][p].z, bh[0][p].w);
            }
        }
        #pragma unroll
        for (int mt = 0; mt < 2; mt++) {
            LDMATRIX_X4(ah[mt], stg + aOff[mt][1]);
            LDMATRIX_X4(al[mt], stg + aOff[mt][1] + A_TILE);
        }
        #pragma unroll
        for (int mt = 0; mt < 2; mt++) {
            #pragma unroll
            for (int p = 0; p < 2; p++) {
                MMA_BF16(acc[mt][2*p],   ah[mt], bh[1][p].x, bh[1][p].y);
                MMA_BF16(acc[mt][2*p],   ah[mt], bl[1][p].x, bl[1][p].y);
                MMA_BF16(acc[mt][2*p],   al[mt], bh[1][p].x, bh[1][p].y);
                MMA_BF16(acc[mt][2*p+1], ah[mt], bh[1][p].z, bh[1][p].w);
                MMA_BF16(acc[mt][2*p+1], ah[mt], bl[1][p].z, bl[1][p].w);
                MMA_BF16(acc[mt][2*p+1], al[mt], bh[1][p].z, bh[1][p].w);
            }
        }
    };

    // prologue
    loadG(0); storeS(0, 0);
    loadG(1); storeS(1, 1);
    __syncthreads();

    // mainloop: one barrier per 2 K-blocks
    #pragma unroll 1
    for (int kbp = 0; kbp < 8; kbp += 2) {
        if (kbp + 2 < 8) loadG(kbp + 2);
        consume(kbp & 3);
        if (kbp + 2 < 8) storeS((kbp + 2) & 3, kbp + 2);
        if (kbp + 3 < 8) loadG(kbp + 3);
        consume((kbp + 1) & 3);
        if (kbp + 3 < 8) storeS((kbp + 3) & 3, kbp + 3);
        if (kbp + 2 < 8) __syncthreads();
    }

    // epilogue: +bias, store, fused per-channel stats
    float sp[8], ssp[8];
    #pragma unroll
    for (int c = 0; c < 8; c++) { sp[c] = 0.f; ssp[c] = 0.f; }

    const int gId = lane >> 2, l4 = lane & 3;
    #pragma unroll
    for (int mt = 0; mt < 2; mt++) {
        size_t row0 = rowBase + wm * 32 + mt * 16 + gId;
        #pragma unroll
        for (int nt = 0; nt < 4; nt++) {
            int col0 = colBase + wn * 32 + nt * 8 + 2 * l4;
            float b0 = bias[col0], b1 = bias[col0 + 1];
            float v00 = acc[mt][nt][0] + b0, v01 = acc[mt][nt][1] + b1;
            float v10 = acc[mt][nt][2] + b0, v11 = acc[mt][nt][3] + b1;
            *(float2*)(out + row0 * O + col0)        = make_float2(v00, v01);
            *(float2*)(out + (row0 + 8) * O + col0)  = make_float2(v10, v11);
            sp[nt * 2 + 0]  += v00 + v10;
            sp[nt * 2 + 1]  += v01 + v11;
            ssp[nt * 2 + 0] += v00 * v00 + v10 * v10;
            ssp[nt * 2 + 1] += v01 * v01 + v11 * v11;
        }
    }
    #pragma unroll
    for (int c = 0; c < 8; c++) {
        #pragma unroll
        for (int mask = 4; mask <= 16; mask <<= 1) {
            sp[c]  += __shfl_xor_sync(0xffffffffu, sp[c],  mask);
            ssp[c] += __shfl_xor_sync(0xffffffffu, ssp[c], mask);
        }
    }
    if (lane < 4) {
        #pragma unroll
        for (int nt = 0; nt < 4; nt++) {
            #pragma unroll
            for (int h = 0; h < 2; h++) {
                int col = colBase + wn * 32 + nt * 8 + 2 * lane + h;
                atomicAdd(&sumArr[col],   sp[nt * 2 + h]);
                atomicAdd(&sumsqArr[col], ssp[nt * 2 + h]);
            }
        }
    }
}

// ---------------------------------------------------------------------------
// final BN+ReLU + transpose [b][n][o] -> [b][o][n] into d_out (O = 128).
__global__ void output_kernel(const float* __restrict__ in, float* __restrict__ out) {
    __shared__ float t[32][33];
    const int b = blockIdx.z;
    const int n0 = blockIdx.x * 32, o0 = blockIdx.y * 32;
    const int tx = threadIdx.x, ty = threadIdx.y; // 32 x 8
    #pragma unroll
    for (int k = 0; k < 32; k += 8) {
        int o = o0 + tx;
        float v = in[((size_t)b * Np + n0 + ty + k) * 128 + o];
        t[ty + k][tx] = fmaxf(fmaf(v, g_scale[o], g_shift[o]), 0.f);
    }
    __syncthreads();
    #pragma unroll
    for (int k = 0; k < 32; k += 8)
        out[((size_t)b * 128 + o0 + ty + k) * Np + n0 + tx] = t[tx][ty + k];
}

// ---------------------------------------------------------------------------
extern "C" void kernel_launch(void* const* d_in, const int* in_sizes, int n_in,
                              void* d_out, int out_size) {
    const float* p   = (const float*)d_in[0];
    const float* q   = (const float*)d_in[1];
    const float* x   = (const float*)d_in[2];
    const float* w0  = (const float*)d_in[3];
    const float* b0  = (const float*)d_in[4];
    const float* g0  = (const float*)d_in[5];
    const float* be0 = (const float*)d_in[6];
    const float* w1  = (const float*)d_in[7];
    const float* b1  = (const float*)d_in[8];
    const float* g1  = (const float*)d_in[9];
    const float* be1 = (const float*)d_in[10];
    const float* w2  = (const float*)d_in[11];
    const float* b2  = (const float*)d_in[12];
    const float* g2  = (const float*)d_in[13];
    const float* be2 = (const float*)d_in[14];
    float* out = (float*)d_out;

    float *bufA, *bufB, *xT;
    uint4* wcv;
    float *sum0, *sumsq0, *sum1, *sumsq1, *sum2, *sumsq2;
    cudaGetSymbolAddress((void**)&bufA, g_bufA);
    cudaGetSymbolAddress((void**)&bufB, g_bufB);
    cudaGetSymbolAddress((void**)&xT,  g_xT);
    cudaGetSymbolAddress((void**)&wcv, g_wcv);
    cudaGetSymbolAddress((void**)&sum0, g_sum0);
    cudaGetSymbolAddress((void**)&sumsq0, g_sumsq0);
    cudaGetSymbolAddress((void**)&sum1, g_sum1);
    cudaGetSymbolAddress((void**)&sumsq1, g_sumsq1);
    cudaGetSymbolAddress((void**)&sum2, g_sum2);
    cudaGetSymbolAddress((void**)&sumsq2, g_sumsq2);

    const int Qfloats = Bb * Mp * 3;                    // 24576
    const int Hfloats = Bb * 128 * Np;                  // 8388608
    const int qoff = (out_size >= Qfloats + Hfloats) ? Qfloats : 0;

    cudaFuncSetAttribute(gemm_bf16x3_kernel,
                         cudaFuncAttributeMaxDynamicSharedMemorySize, SMEM_GEMM_BYTES);

    zero_stats_kernel<<<1, 256>>>();
    wconv_kernel<<<40, 512>>>(w0, w1, w2, wcv);
    transpose_x_kernel<<<dim3(Mp / 32, Cc / 32, Bb), dim3(32, 8)>>>(x, xT);
    knn_interp_kernel<<<dim3(Bb, Np / 128), 512>>>(p, q, xT, bufA);

    // layer 0: in bufA (raw), out bufB (256 ch) — stats fused
    gemm_bf16x3_kernel<<<dim3(Rr / 64, 2), 256, SMEM_GEMM_BYTES>>>(
        bufA, wcv, b0, 0, bufB, 256, sum0, sumsq0);
    bn_finalize_kernel<<<1, 256>>>(sum0, sumsq0, g0, be0, 256);

    // layer 1: in bufB (BN0+ReLU via g_scale/g_shift), out bufA (256 ch)
    gemm_bf16x3_kernel<<<dim3(Rr / 64, 2), 256, SMEM_GEMM_BYTES>>>(
        bufB, wcv + 16 * 1024, b1, 1, bufA, 256, sum1, sumsq1);
    bn_finalize_kernel<<<1, 256>>>(sum1, sumsq1, g1, be1, 256);

    // layer 2: in bufA (BN1+ReLU via g_scale/g_shift), out bufB (128 ch)
    gemm_bf16x3_kernel<<<dim3(Rr / 64, 1), 256, SMEM_GEMM_BYTES>>>(
        bufA, wcv + 32 * 1024, b2, 1, bufB, 128, sum2, sumsq2);
    bn_finalize_kernel<<<1, 256>>>(sum2, sumsq2, g2, be2, 128);

    // output: [q | BN2+ReLU(h) transposed to [B,128,N]]
    if (qoff)
        cudaMemcpyAsync(out, q, (size_t)Qfloats * sizeof(float),
                        cudaMemcpyDeviceToDevice);
    output_kernel<<<dim3(Np / 32, 4, Bb), dim3(32, 8)>>>(bufB, out + qoff);
}